// round 7
// baseline (speedup 1.0000x reference)
#include <cuda_runtime.h>
#include <math.h>

// Split-KV (flash-decoding) stage-2 merge. B=256, H=32, S=16, D=128, fp32.
//
// R6 design point (from R5 ncu: occ=62%, issue=23.8%, DRAM=40% -> per-warp
// serial-latency bound, not occupancy bound):
//   * TWO heads per warp (same batch b -> geometry computed once, amortized)
//   * LSE for both heads = ONE coalesced 128B load (lanes 0-15 head0, 16-31 head1)
//   * half-warp xor reductions (offsets 8,4,2,1) reduce BOTH heads in 4 steps
//   * 8 LDG.E.128 in flight per s-batch (4 per head), 2 accumulators
//   * 4096 warps -> 1024 blocks x 128 thr = single wave (~28 warps/SM)
//   * unsigned division (cheaper emulation than signed)

#define B_DIM 256
#define H_DIM 32
#define S_DIM 16
#define D_DIM 128
#define LOG2E 1.4426950408889634f

__global__ __launch_bounds__(128)
void splitkv_merge_kernel(const float* __restrict__ att_out,
                          const float* __restrict__ att_lse,
                          const int*   __restrict__ kv_indptr,
                          const int*   __restrict__ num_kv_splits,
                          float*       __restrict__ out)
{
    const unsigned pair_id = (blockIdx.x * 128u + threadIdx.x) >> 5;  // (b, head-pair)
    const unsigned lane    = threadIdx.x & 31u;
    const unsigned b       = pair_id >> 4;        // 16 head-pairs per batch
    const unsigned sl      = lane & 15u;          // split index within my half

    // ---- geometry: once per warp, shared by both heads (unsigned div) ----
    const unsigned seq_len = (unsigned)(kv_indptr[b + 1] - kv_indptr[b]);
    const unsigned splits  = (unsigned)num_kv_splits[b];
    const unsigned per_split = ((((seq_len + splits - 1u) / splits) + 31u) >> 5) << 5;
    const unsigned nv = (seq_len + per_split - 1u) / per_split;   // 1..16 valid prefix

    // ---- LSE for both heads: one coalesced 128B load ----
    // att_lse[(b*32 + h0 + (lane>>4)) * 16 + sl] == att_lse[pair_id*32 + lane]
    float lse_raw = att_lse[pair_id * 32u + lane];
    float lse = (sl < nv) ? lse_raw : -INFINITY;

    // half-warp reductions: offsets 8,4,2,1 keep each 16-lane half independent,
    // so head0 (lanes 0-15) and head1 (lanes 16-31) reduce simultaneously.
    float m = lse;
    #pragma unroll
    for (int o = 8; o > 0; o >>= 1)
        m = fmaxf(m, __shfl_xor_sync(0xffffffffu, m, o));

    float w = (sl < nv) ? exp2f((lse - m) * LOG2E) : 0.0f;

    float esum = w;
    #pragma unroll
    for (int o = 8; o > 0; o >>= 1)
        esum += __shfl_xor_sync(0xffffffffu, esum, o);

    const float inv  = 1.0f / esum;
    const float inv0 = __shfl_sync(0xffffffffu, inv, 0);   // head0's 1/esum
    const float inv1 = __shfl_sync(0xffffffffu, inv, 16);  // head1's 1/esum

    // ---- weighted accumulation: 8 loads in flight per s-batch ----
    // att_out rows: head0 base = pair_id*2*(16*32) float4, head1 = +512 float4.
    const float4* __restrict__ src0 =
        reinterpret_cast<const float4*>(att_out) + pair_id * 1024u + lane;
    const float4* __restrict__ src1 = src0 + 512u;

    float4 a0 = make_float4(0.f, 0.f, 0.f, 0.f);
    float4 a1 = make_float4(0.f, 0.f, 0.f, 0.f);

    #pragma unroll
    for (int s0 = 0; s0 < S_DIM; s0 += 4) {
        if (s0 < (int)nv) {                     // warp-uniform batch skip
            float4 u0, u1, u2, u3, v0, v1, v2, v3;
            u0 = u1 = u2 = u3 = make_float4(0.f, 0.f, 0.f, 0.f);
            v0 = v1 = v2 = v3 = make_float4(0.f, 0.f, 0.f, 0.f);
            // front-batched predicated loads: 8 x LDG.E.128
            if (s0 + 0 < (int)nv) { u0 = src0[(s0 + 0) * 32]; v0 = src1[(s0 + 0) * 32]; }
            if (s0 + 1 < (int)nv) { u1 = src0[(s0 + 1) * 32]; v1 = src1[(s0 + 1) * 32]; }
            if (s0 + 2 < (int)nv) { u2 = src0[(s0 + 2) * 32]; v2 = src1[(s0 + 2) * 32]; }
            if (s0 + 3 < (int)nv) { u3 = src0[(s0 + 3) * 32]; v3 = src1[(s0 + 3) * 32]; }

            float w0, w1;
            w0 = __shfl_sync(0xffffffffu, w, s0 + 0);
            w1 = __shfl_sync(0xffffffffu, w, 16 + s0 + 0);
            a0.x = fmaf(w0, u0.x, a0.x); a0.y = fmaf(w0, u0.y, a0.y);
            a0.z = fmaf(w0, u0.z, a0.z); a0.w = fmaf(w0, u0.w, a0.w);
            a1.x = fmaf(w1, v0.x, a1.x); a1.y = fmaf(w1, v0.y, a1.y);
            a1.z = fmaf(w1, v0.z, a1.z); a1.w = fmaf(w1, v0.w, a1.w);

            w0 = __shfl_sync(0xffffffffu, w, s0 + 1);
            w1 = __shfl_sync(0xffffffffu, w, 16 + s0 + 1);
            a0.x = fmaf(w0, u1.x, a0.x); a0.y = fmaf(w0, u1.y, a0.y);
            a0.z = fmaf(w0, u1.z, a0.z); a0.w = fmaf(w0, u1.w, a0.w);
            a1.x = fmaf(w1, v1.x, a1.x); a1.y = fmaf(w1, v1.y, a1.y);
            a1.z = fmaf(w1, v1.z, a1.z); a1.w = fmaf(w1, v1.w, a1.w);

            w0 = __shfl_sync(0xffffffffu, w, s0 + 2);
            w1 = __shfl_sync(0xffffffffu, w, 16 + s0 + 2);
            a0.x = fmaf(w0, u2.x, a0.x); a0.y = fmaf(w0, u2.y, a0.y);
            a0.z = fmaf(w0, u2.z, a0.z); a0.w = fmaf(w0, u2.w, a0.w);
            a1.x = fmaf(w1, v2.x, a1.x); a1.y = fmaf(w1, v2.y, a1.y);
            a1.z = fmaf(w1, v2.z, a1.z); a1.w = fmaf(w1, v2.w, a1.w);

            w0 = __shfl_sync(0xffffffffu, w, s0 + 3);
            w1 = __shfl_sync(0xffffffffu, w, 16 + s0 + 3);
            a0.x = fmaf(w0, u3.x, a0.x); a0.y = fmaf(w0, u3.y, a0.y);
            a0.z = fmaf(w0, u3.z, a0.z); a0.w = fmaf(w0, u3.w, a0.w);
            a1.x = fmaf(w1, v3.x, a1.x); a1.y = fmaf(w1, v3.y, a1.y);
            a1.z = fmaf(w1, v3.z, a1.z); a1.w = fmaf(w1, v3.w, a1.w);
        }
    }

    a0.x *= inv0; a0.y *= inv0; a0.z *= inv0; a0.w *= inv0;
    a1.x *= inv1; a1.y *= inv1; a1.z *= inv1; a1.w *= inv1;

    float4* __restrict__ dst = reinterpret_cast<float4*>(out) + pair_id * 64u + lane;
    dst[0]  = a0;   // head0: pair_id*64 + lane
    dst[32] = a1;   // head1: +32 float4
}

extern "C" void kernel_launch(void* const* d_in, const int* in_sizes, int n_in,
                              void* d_out, int out_size)
{
    const float* att_out       = (const float*)d_in[0];
    const float* att_lse       = (const float*)d_in[1];
    // d_in[2] = q, d_in[3] = v_buffer : unused (shape-only in the reference)
    const int*   kv_indptr     = (const int*)d_in[4];
    const int*   num_kv_splits = (const int*)d_in[5];
    float*       out           = (float*)d_out;

    // 4096 head-pair warps, 4 warps per 128-thread block -> 1024 blocks exact
    splitkv_merge_kernel<<<(B_DIM * H_DIM / 2) / 4, 128>>>(att_out, att_lse,
                                                           kv_indptr, num_kv_splits, out);
}